// round 7
// baseline (speedup 1.0000x reference)
#include <cuda_runtime.h>

// DepthwiseRREUp: groups=C*G conv_transpose2d, kernel=stride=2, pad=0.
// out[b,c,g, 2i+di, 2j+dj] = x[b,c,g,i,j] * rot90(dw[c], g)[di][dj]
//
// x:  [B=8, C=256, G=4, H=64, W=64] fp32
// dw: [C=256, 1, 2, 2] fp32 (tiny, cache-resident)
// out:[B, C, G, 128, 128] fp32
//
// OUTPUT-CENTRIC: one thread per output float4 (4 consecutive output cols
// of one output row). That quad needs exactly 2 consecutive input floats
// (one float2) from one input row:
//   out[oi, 4q..4q+3] = (x2.x*fa, x2.x*fb, x2.y*fa, x2.y*fb)
// where (fa,fb) is row (oi&1) of the g-rotated 2x2 filter.
//
// Both LDG.64 and STG.128 are lane-contiguous -> fully-filled 128B
// wavefronts (the previous input-centric kernel's stores were 32B-strided
// across lanes = half-filled lines = 2x L1tex wavefronts; L1 was the
// bottleneck at 82.9% while DRAM idled at 66.6%).
// Input is touched twice (rows 2i and 2i+1) but the second touch is 32
// warps later in the same block -> L1/L2 hit; DRAM traffic unchanged.

__global__ void __launch_bounds__(256)
DepthwiseRREUp_40106404610493_kernel(const float2* __restrict__ x2,
                                     const float4* __restrict__ dw4,  // [C] of (a,b,c,d)
                                     float4* __restrict__ out4,
                                     int total4) {
    int o = blockIdx.x * blockDim.x + threadIdx.x;
    if (o >= total4) return;

    // Output plane = 128*128 floats = 4096 float4 (32 quads per row).
    int q     = o & 31;           // quad within output row
    int oi    = (o >> 5) & 127;   // output row
    int plane = o >> 12;          // linear (b,c,g)
    int g     = plane & 3;        // warp-uniform
    int c     = (plane >> 2) & 255;

    int i  = oi >> 1;             // input row
    int di = oi & 1;              // filter row

    // Input plane = 64*64 floats = 2048 float2 (32 float2 per row).
    float2 xv = x2[plane * 2048 + i * 32 + q];
    float4 w  = dw4[c];           // a=w.x b=w.y c=w.z d=w.w (row-major 2x2)

    // numpy rot90 (CCW) k=g of [[a,b],[c,d]]:
    //   g=0: a b / c d    g=1: b d / a c
    //   g=2: d c / b a    g=3: c a / d b
    float f00, f01, f10, f11;
    switch (g) {
        case 0:  f00 = w.x; f01 = w.y; f10 = w.z; f11 = w.w; break;
        case 1:  f00 = w.y; f01 = w.w; f10 = w.x; f11 = w.z; break;
        case 2:  f00 = w.w; f01 = w.z; f10 = w.y; f11 = w.x; break;
        default: f00 = w.z; f01 = w.x; f10 = w.w; f11 = w.y; break;
    }
    float fa = di ? f10 : f00;
    float fb = di ? f11 : f01;

    out4[o] = make_float4(xv.x * fa, xv.x * fb, xv.y * fa, xv.y * fb);
}

extern "C" void kernel_launch(void* const* d_in, const int* in_sizes, int n_in,
                              void* d_out, int out_size) {
    const float2* x2  = (const float2*)d_in[0];
    const float4* dw4 = (const float4*)d_in[1];
    float4* out4      = (float4*)d_out;

    int total4 = out_size / 4;                    // 33,554,432 output quads
    int threads = 256;
    int blocks = (total4 + threads - 1) / threads;
    DepthwiseRREUp_40106404610493_kernel<<<blocks, threads>>>(x2, dw4, out4, total4);
}

// round 8
// speedup vs baseline: 1.1907x; 1.1907x over previous
#include <cuda_runtime.h>

// DepthwiseRREUp: groups=C*G conv_transpose2d, kernel=stride=2, pad=0.
// out[b,c,g, 2i+di, 2j+dj] = x[b,c,g,i,j] * rot90(dw[c], g)[di][dj]
//
// x:  [B=8, C=256, G=4, H=64, W=64] fp32     (128 MiB)
// dw: [C=256, 1, 2, 2] fp32                  (cache-resident)
// out:[B, C, G, 128, 128] fp32               (512 MiB)
//
// Mapping: output row = 128 floats = 32 float4 quads = 32 lanes.
//   lane  = quad index q (0..31)
//   thread covers 4 consecutive output rows (oi0..oi0+3) at quad q.
// => every STG.128 across a warp covers 32 consecutive quads (512 B
//    contiguous, fully-filled 128B lines); every LDG.64 covers 256 B
//    contiguous. Input rows i0, i0+1 are each read EXACTLY ONCE chip-wide.
// Per thread: 2x LDG.64 + 4x STG.128 (6 independent memory ops in flight),
// index math + rot90 select amortized over 64 B of output.
// __ldcs/__stcs: pure streaming data, evict-first, keep L2 clean for the
// 4:1 write:read mix.

__global__ void __launch_bounds__(256)
DepthwiseRREUp_40106404610493_kernel(const float2* __restrict__ x2,
                                     const float4* __restrict__ dw4,  // [C] of (a,b,c,d)
                                     float4* __restrict__ out4,
                                     int nthreads) {
    int t = blockIdx.x * blockDim.x + threadIdx.x;
    if (t >= nthreads) return;

    int q     = t & 31;          // quad within row == lane
    int rg    = t >> 5;          // row-group: 4 output rows
    int oi0   = (rg & 31) << 2;  // first output row (0..124, step 4)
    int plane = rg >> 5;         // linear (b,c,g)
    int g     = plane & 3;       // warp-uniform
    int c     = (plane >> 2) & 255;

    // Input rows i0 = oi0/2, i0+1. Input plane = 2048 float2, 32 per row.
    int ibase = plane * 2048 + (oi0 >> 1) * 32 + q;
    float2 xa = __ldcs(&x2[ibase]);        // input row i0
    float2 xb = __ldcs(&x2[ibase + 32]);   // input row i0+1

    float4 w = dw4[c];  // a=w.x b=w.y c=w.z d=w.w (row-major 2x2)

    // numpy rot90 (CCW) k=g of [[a,b],[c,d]]:
    //   g=0: a b / c d    g=1: b d / a c
    //   g=2: d c / b a    g=3: c a / d b
    float f00, f01, f10, f11;
    switch (g) {
        case 0:  f00 = w.x; f01 = w.y; f10 = w.z; f11 = w.w; break;
        case 1:  f00 = w.y; f01 = w.w; f10 = w.x; f11 = w.z; break;
        case 2:  f00 = w.w; f01 = w.z; f10 = w.y; f11 = w.x; break;
        default: f00 = w.z; f01 = w.x; f10 = w.w; f11 = w.y; break;
    }

    // Output plane = 4096 float4, 32 per row.
    int obase = plane * 4096 + oi0 * 32 + q;
    __stcs(&out4[obase],      make_float4(xa.x * f00, xa.x * f01, xa.y * f00, xa.y * f01));
    __stcs(&out4[obase + 32], make_float4(xa.x * f10, xa.x * f11, xa.y * f10, xa.y * f11));
    __stcs(&out4[obase + 64], make_float4(xb.x * f00, xb.x * f01, xb.y * f00, xb.y * f01));
    __stcs(&out4[obase + 96], make_float4(xb.x * f10, xb.x * f11, xb.y * f10, xb.y * f11));
}

extern "C" void kernel_launch(void* const* d_in, const int* in_sizes, int n_in,
                              void* d_out, int out_size) {
    const float2* x2  = (const float2*)d_in[0];
    const float4* dw4 = (const float4*)d_in[1];
    float4* out4      = (float4*)d_out;

    int nthreads = out_size / 16;                 // out_size/4 quads / 4 per thread
    int threads = 256;
    int blocks = (nthreads + threads - 1) / threads;
    DepthwiseRREUp_40106404610493_kernel<<<blocks, threads>>>(x2, dw4, out4, nthreads);
}